// round 12
// baseline (speedup 1.0000x reference)
#include <cuda_runtime.h>
#include <cuda_fp16.h>
#include <cstdint>

// Problem dims: S=4, B=512 -> M=2048; D=256; H=1024; T=50 -> 49 RK4 steps
#define MROWS 2048
#define DDIM  256
#define HDIM  1024
#define TPTS  50
#define NSTEPS (TPTS - 1)
#define NCTAS 128
#define ROWB 144

// ==================== device scratch ====================
__device__ float g_y [MROWS * DDIM];
__device__ float g_k1[MROWS * DDIM];
__device__ float g_k2[MROWS * DDIM];
__device__ float g_k3[MROWS * DDIM];
__device__ __half g_yq [MROWS * DDIM];
__device__ __half g_ytq[MROWS * DDIM];
__device__ __half g_h1q[MROWS * HDIM];
__device__ __half g_h2q[MROWS * HDIM];
__device__ __half g_w1[HDIM * DDIM];
__device__ __half g_w2[HDIM * HDIM];
__device__ __half g_w3[DDIM * HDIM];

// grid barrier state (self-resetting; graph-replay safe)
__device__ int g_bar_count;
__device__ int g_bar_gen;

// fast tanh: 1 - 2/(e^{2x}+1)
__device__ __forceinline__ float tanh_fast(float x) {
    float e;
    asm("ex2.approx.f32 %0, %1;" : "=f"(e) : "f"(x * 2.8853900817779268f));
    float r;
    asm("rcp.approx.f32 %0, %1;" : "=f"(r) : "f"(e + 1.0f));
    return fmaf(-2.0f, r, 1.0f);
}

__device__ __forceinline__ uint32_t smem_u32(const void* p) {
    uint32_t a;
    asm("{ .reg .u64 t; cvta.to.shared.u64 t, %1; cvt.u32.u64 %0, t; }" : "=r"(a) : "l"(p));
    return a;
}
__device__ __forceinline__ void cp_async16(uint32_t dst, const void* src) {
    asm volatile("cp.async.cg.shared.global [%0], [%1], 16;" :: "r"(dst), "l"(src) : "memory");
}
__device__ __forceinline__ void cp_commit() {
    asm volatile("cp.async.commit_group;" ::: "memory");
}
template<int N>
__device__ __forceinline__ void cp_wait() {
    asm volatile("cp.async.wait_group %0;" :: "n"(N) : "memory");
}
__device__ __forceinline__ void ldsm_x4(uint32_t& r0, uint32_t& r1, uint32_t& r2, uint32_t& r3,
                                        uint32_t addr) {
    asm volatile("ldmatrix.sync.aligned.m8n8.x4.shared.b16 {%0,%1,%2,%3}, [%4];"
                 : "=r"(r0), "=r"(r1), "=r"(r2), "=r"(r3) : "r"(addr));
}
__device__ __forceinline__ void mma_fp16(float* c, uint32_t a0, uint32_t a1, uint32_t a2,
                                         uint32_t a3, uint32_t b0, uint32_t b1) {
    asm volatile("mma.sync.aligned.m16n8k16.row.col.f32.f16.f16.f32 "
                 "{%0,%1,%2,%3}, {%4,%5,%6,%7}, {%8,%9}, {%0,%1,%2,%3};"
                 : "+f"(c[0]), "+f"(c[1]), "+f"(c[2]), "+f"(c[3])
                 : "r"(a0), "r"(a1), "r"(a2), "r"(a3), "r"(b0), "r"(b1));
}

// generation-based grid barrier; also orders prior global stores (threadfence)
__device__ __forceinline__ void grid_barrier() {
    __syncthreads();
    if (threadIdx.x == 0) {
        __threadfence();
        int gen = *((volatile int*)&g_bar_gen);
        if (atomicAdd(&g_bar_count, 1) == NCTAS - 1) {
            *((volatile int*)&g_bar_count) = 0;
            __threadfence();
            atomicAdd(&g_bar_gen, 1);
        } else {
            while (*((volatile int*)&g_bar_gen) == gen) { }
        }
        __threadfence();
    }
    __syncthreads();
}

// prefetch next phase's B chunk-0 into stage0 B region (one cp.async group)
__device__ __forceinline__ void prefetch_B0(const __half* __restrict__ B, int K,
                                            int colBase, int BN_, uint32_t dstB, int tid) {
    const int units = BN_ * 8;      // 16B units
    for (int idx = tid; idx < units; idx += 256) {
        int r = idx >> 3, q = idx & 7;
        cp_async16(dstB + (uint32_t)(r * ROWB + q * 16),
                   B + (size_t)(colBase + r) * K + q * 8);
    }
    cp_commit();
}

// ==================== generic GEMM phase (R8 champion body) ====================
// Entry contract: exactly ONE outstanding cp.async group = this phase's B chunk-0
// (already in stage0 B region). EPI: 0=tanh->Ch(half,N-stride), 1=k+axpy, 2=RK4 final.
template<int BM, int BN, int NCH, int EPI>
__device__ __forceinline__ void gemm_phase(
    const __half* __restrict__ A, const __half* __restrict__ B,
    const float* __restrict__ bias,
    __half* __restrict__ Ch,
    float* __restrict__ y, float* __restrict__ kout,
    const float* __restrict__ k1, const float* __restrict__ k2,
    const float* __restrict__ k3,
    __half* __restrict__ outq, float* __restrict__ pred,
    const float* __restrict__ t, int step, float coef,
    int N, uint32_t sbase, int bid, int tid)
{
    constexpr int K  = NCH * 64;
    constexpr int WR = BM / 32;
    constexpr int WC = 8 / WR;
    constexpr int WN = BN / WC;
    constexpr int NT = WN / 8;
    constexpr int BUF = (BM + BN) * ROWB;
    const int colBlocks = N / BN;
    const int rowBase = (bid / colBlocks) * BM;
    const int colBase = (bid % colBlocks) * BN;
    const int wid = tid >> 5, lane = tid & 31;
    const int wm = wid % WR, wn = wid / WR;
    const uint32_t offA = 0;
    const uint32_t offB = (uint32_t)BM * ROWB;

    auto load_A = [&](int c) {
        const uint32_t stage = sbase + (uint32_t)(c & 1) * BUF;
        const int kbase = c << 6;
        #pragma unroll
        for (int u = 0; u < BM * 8 / 256; u++) {
            int idx = tid + u * 256;
            int r = idx >> 3, q = idx & 7;
            cp_async16(stage + offA + (uint32_t)(r * ROWB + q * 16),
                       A + (size_t)(rowBase + r) * K + kbase + q * 8);
        }
    };
    auto load_B = [&](int c) {
        const uint32_t stage = sbase + (uint32_t)(c & 1) * BUF;
        const int kbase = c << 6;
        #pragma unroll
        for (int u = 0; u < BN * 8 / 256; u++) {
            int idx = tid + u * 256;
            int r = idx >> 3, q = idx & 7;
            cp_async16(stage + offB + (uint32_t)(r * ROWB + q * 16),
                       B + (size_t)(colBase + r) * K + kbase + q * 8);
        }
    };

    load_A(0);
    cp_commit();

    float acc[2][NT][4];
    #pragma unroll
    for (int mt = 0; mt < 2; mt++)
        #pragma unroll
        for (int nt = 0; nt < NT; nt++)
            #pragma unroll
            for (int j = 0; j < 4; j++)
                acc[mt][nt][j] = 0.0f;

    const int aRow = wm * 32 + (lane & 15);
    const int aByte = (lane & 16);
    const int bRow = wn * WN + ((lane & 16) >> 1) + (lane & 7);
    const int bByte = ((lane & 8) << 1);

    for (int c = 0; c < NCH; c++) {
        if (c + 1 < NCH) {
            load_A(c + 1); load_B(c + 1); cp_commit();
            cp_wait<1>();
        } else {
            cp_wait<0>();
        }
        __syncthreads();

        const uint32_t stage = sbase + (uint32_t)(c & 1) * BUF;
        #pragma unroll
        for (int ks = 0; ks < 4; ks++) {
            uint32_t a[2][4];
            #pragma unroll
            for (int mt = 0; mt < 2; mt++) {
                uint32_t ad = stage + (uint32_t)((aRow + mt * 16) * ROWB + ks * 32 + aByte);
                ldsm_x4(a[mt][0], a[mt][1], a[mt][2], a[mt][3], ad + offA);
            }
            uint32_t bb[NT][2];
            #pragma unroll
            for (int nt2 = 0; nt2 < NT / 2; nt2++) {
                uint32_t bd = stage + (uint32_t)((bRow + nt2 * 16) * ROWB + ks * 32 + bByte);
                ldsm_x4(bb[nt2 * 2][0], bb[nt2 * 2][1], bb[nt2 * 2 + 1][0], bb[nt2 * 2 + 1][1],
                        bd + offB);
            }
            #pragma unroll
            for (int mt = 0; mt < 2; mt++)
                #pragma unroll
                for (int nt = 0; nt < NT; nt++)
                    mma_fp16(acc[mt][nt], a[mt][0], a[mt][1], a[mt][2], a[mt][3],
                             bb[nt][0], bb[nt][1]);
        }
        __syncthreads();
    }

    const float dtv = (EPI != 0) ? (t[step + 1] - t[step]) : 0.0f;
    const float cax = coef * dtv;
    const float s6 = dtv * (1.0f / 6.0f);
    const int q = lane >> 2;
    const int p = lane & 3;
    #pragma unroll
    for (int mt = 0; mt < 2; mt++) {
        #pragma unroll
        for (int half = 0; half < 2; half++) {
            const int row = rowBase + wm * 32 + mt * 16 + q + half * 8;
            #pragma unroll
            for (int nt = 0; nt < NT; nt++) {
                const int col = colBase + wn * WN + nt * 8 + p * 2;
                const size_t gi = (size_t)row * N + col;
                float v0 = acc[mt][nt][half * 2 + 0] + bias[col + 0];
                float v1 = acc[mt][nt][half * 2 + 1] + bias[col + 1];
                if (EPI == 0) {
                    v0 = tanh_fast(v0); v1 = tanh_fast(v1);
                    *(__half2*)(Ch + gi) = __floats2half2_rn(v0, v1);
                } else if (EPI == 1) {
                    *(float2*)(kout + gi) = make_float2(v0, v1);
                    float2 yv = *(const float2*)(y + gi);
                    float o0 = fmaf(cax, v0, yv.x);
                    float o1 = fmaf(cax, v1, yv.y);
                    *(__half2*)(outq + gi) = __floats2half2_rn(o0, o1);
                } else {
                    float2 yv = *(const float2*)(y + gi);
                    float2 a1 = *(const float2*)(k1 + gi);
                    float2 a2 = *(const float2*)(k2 + gi);
                    float2 a3 = *(const float2*)(k3 + gi);
                    float o0 = yv.x + s6 * (a1.x + 2.0f * a2.x + 2.0f * a3.x + v0);
                    float o1 = yv.y + s6 * (a1.y + 2.0f * a2.y + 2.0f * a3.y + v1);
                    *(float2*)(y + gi) = make_float2(o0, o1);
                    *(__half2*)(outq + gi) = __floats2half2_rn(o0, o1);
                    *(float2*)(pred + ((size_t)row * TPTS + (step + 1)) * DDIM + col) =
                        make_float2(o0, o1);
                }
            }
        }
    }
}

// ==================== persistent mega-kernel: all 49 RK4 steps ====================
#define MEGA_SMEM (2 * (128 + 128) * ROWB)   // 73728 (max of L1/L2 and L3 stages)

__global__ __launch_bounds__(256)
void mega_kernel(const float* __restrict__ t,
                 const float* __restrict__ b1, const float* __restrict__ b2,
                 const float* __restrict__ b3, float* __restrict__ out)
{
    extern __shared__ char smem[];
    const uint32_t sbase = smem_u32(smem);
    const int tid = threadIdx.x, bid = blockIdx.x;
    const int cb8 = (bid % 8) * 128;    // colBase for 128-wide phases
    const int cb4 = (bid % 4) * 64;     // colBase for 64-wide phases

    // prefetch B0 for the very first phase (L1)
    prefetch_B0(g_w1, DDIM, cb8, 128, sbase + 128u * ROWB, tid);

    for (int s = 0; s < NSTEPS; s++) {
        for (int sub = 0; sub < 4; sub++) {
            const __half* x = (sub == 0) ? g_yq : g_ytq;

            // L1: h1 = tanh(x @ W1 + b1)     [2048x256 @ 256x1024]
            gemm_phase<128, 128, 4, 0>(x, g_w1, b1, g_h1q,
                                       nullptr, nullptr, nullptr, nullptr, nullptr,
                                       nullptr, nullptr, t, s, 0.0f,
                                       HDIM, sbase, bid, tid);
            prefetch_B0(g_w2, HDIM, cb8, 128, sbase + 128u * ROWB, tid);
            grid_barrier();

            // L2: h2 = tanh(h1 @ W2 + b2)    [2048x1024 @ 1024x1024]
            gemm_phase<128, 128, 16, 0>(g_h1q, g_w2, b2, g_h2q,
                                        nullptr, nullptr, nullptr, nullptr, nullptr,
                                        nullptr, nullptr, t, s, 0.0f,
                                        HDIM, sbase, bid, tid);
            prefetch_B0(g_w3, HDIM, cb4, 64, sbase + 64u * ROWB, tid);
            grid_barrier();

            // L3: k = h2 @ W3 + b3 with fused RK4 epilogue
            if (sub == 0)
                gemm_phase<64, 64, 16, 1>(g_h2q, g_w3, b3, nullptr,
                                          g_y, g_k1, nullptr, nullptr, nullptr,
                                          g_ytq, nullptr, t, s, 0.5f,
                                          DDIM, sbase, bid, tid);
            else if (sub == 1)
                gemm_phase<64, 64, 16, 1>(g_h2q, g_w3, b3, nullptr,
                                          g_y, g_k2, nullptr, nullptr, nullptr,
                                          g_ytq, nullptr, t, s, 0.5f,
                                          DDIM, sbase, bid, tid);
            else if (sub == 2)
                gemm_phase<64, 64, 16, 1>(g_h2q, g_w3, b3, nullptr,
                                          g_y, g_k3, nullptr, nullptr, nullptr,
                                          g_ytq, nullptr, t, s, 1.0f,
                                          DDIM, sbase, bid, tid);
            else
                gemm_phase<64, 64, 16, 2>(g_h2q, g_w3, b3, nullptr,
                                          g_y, nullptr, g_k1, g_k2, g_k3,
                                          g_yq, out, t, s, 0.0f,
                                          DDIM, sbase, bid, tid);

            const bool last = (s == NSTEPS - 1) && (sub == 3);
            if (!last) {
                prefetch_B0(g_w1, DDIM, cb8, 128, sbase + 128u * ROWB, tid);
                grid_barrier();
            }
        }
    }
}

// ==================== weight transpose (once per launch) ====================
__global__ void wsplit_kernel(const float* __restrict__ W, __half* __restrict__ T,
                              int K, int N) {
    int i = blockIdx.x * blockDim.x + threadIdx.x;
    if (i >= K * N) return;
    int k = i / N, n = i % N;
    T[(size_t)n * K + k] = __float2half(W[i]);
}

// ==================== init ====================
__global__ void init_kernel(const float* __restrict__ fp, float* __restrict__ y,
                            __half* __restrict__ yq,
                            float* __restrict__ out, int out_size)
{
    const int i = blockIdx.x * blockDim.x + threadIdx.x;
    float4 v = reinterpret_cast<const float4*>(fp)[i];
    reinterpret_cast<float4*>(y)[i] = v;
    const int e = i * 4;
    *(__half2*)(yq + e + 0) = __floats2half2_rn(v.x, v.y);
    *(__half2*)(yq + e + 2) = __floats2half2_rn(v.z, v.w);
    const int row = e / DDIM;
    const int col = e % DDIM;
    *reinterpret_cast<float4*>(&out[(size_t)row * TPTS * DDIM + col]) = v;
    if (i == 0) {
        const int base = MROWS * TPTS * DDIM;
        for (int z = base; z < out_size; z++) out[z] = 0.0f;
    }
}

// ==================== launch ====================
extern "C" void kernel_launch(void* const* d_in, const int* in_sizes, int n_in,
                              void* d_out, int out_size)
{
    const float* fp = (const float*)d_in[0];
    const float* t  = (const float*)d_in[1];
    const float* W1 = (const float*)d_in[2];
    const float* b1 = (const float*)d_in[3];
    const float* W2 = (const float*)d_in[4];
    const float* b2 = (const float*)d_in[5];
    const float* W3 = (const float*)d_in[6];
    const float* b3 = (const float*)d_in[7];
    float* out = (float*)d_out;

    float* y;
    __half *yq, *w1, *w2, *w3;
    cudaGetSymbolAddress((void**)&y,  g_y);
    cudaGetSymbolAddress((void**)&yq, g_yq);
    cudaGetSymbolAddress((void**)&w1, g_w1);
    cudaGetSymbolAddress((void**)&w2, g_w2);
    cudaGetSymbolAddress((void**)&w3, g_w3);

    cudaFuncSetAttribute((const void*)mega_kernel,
                         cudaFuncAttributeMaxDynamicSharedMemorySize, MEGA_SMEM);

    wsplit_kernel<<<(DDIM * HDIM + 255) / 256, 256>>>(W1, w1, DDIM, HDIM);
    wsplit_kernel<<<(HDIM * HDIM + 255) / 256, 256>>>(W2, w2, HDIM, HDIM);
    wsplit_kernel<<<(HDIM * DDIM + 255) / 256, 256>>>(W3, w3, HDIM, DDIM);

    const int NV4 = (MROWS * DDIM) / 4;
    init_kernel<<<NV4 / 256, 256>>>(fp, y, yq, out, out_size);

    mega_kernel<<<NCTAS, 256, MEGA_SMEM>>>(t, b1, b2, b3, out);
}

// round 13
// speedup vs baseline: 1.1131x; 1.1131x over previous
#include <cuda_runtime.h>
#include <cuda_fp16.h>
#include <cstdint>

// Problem dims: S=4, B=512 -> M=2048; D=256; H=1024; T=50 -> 49 RK4 steps
#define MROWS 2048
#define DDIM  256
#define HDIM  1024
#define TPTS  50
#define NSTEPS (TPTS - 1)

// ==================== device scratch ====================
__device__ float g_y [MROWS * DDIM];
__device__ float g_k1[MROWS * DDIM];
__device__ float g_k2[MROWS * DDIM];
__device__ float g_k3[MROWS * DDIM];
__device__ __half g_yq [MROWS * DDIM];
__device__ __half g_ytq[MROWS * DDIM];
__device__ __half g_h1q[MROWS * HDIM];
__device__ __half g_h2q[MROWS * HDIM];
__device__ __half g_w1[HDIM * DDIM];
__device__ __half g_w2[HDIM * HDIM];
__device__ __half g_w3[DDIM * HDIM];

// fast tanh: 1 - 2/(e^{2x}+1)
__device__ __forceinline__ float tanh_fast(float x) {
    float e;
    asm("ex2.approx.f32 %0, %1;" : "=f"(e) : "f"(x * 2.8853900817779268f));
    float r;
    asm("rcp.approx.f32 %0, %1;" : "=f"(r) : "f"(e + 1.0f));
    return fmaf(-2.0f, r, 1.0f);
}

__device__ __forceinline__ uint32_t smem_u32(const void* p) {
    uint32_t a;
    asm("{ .reg .u64 t; cvta.to.shared.u64 t, %1; cvt.u32.u64 %0, t; }" : "=r"(a) : "l"(p));
    return a;
}
__device__ __forceinline__ void cp_async16(uint32_t dst, const void* src) {
    asm volatile("cp.async.cg.shared.global [%0], [%1], 16;" :: "r"(dst), "l"(src) : "memory");
}
__device__ __forceinline__ void cp_commit() {
    asm volatile("cp.async.commit_group;" ::: "memory");
}
template<int N>
__device__ __forceinline__ void cp_wait() {
    asm volatile("cp.async.wait_group %0;" :: "n"(N) : "memory");
}
__device__ __forceinline__ void ldsm_x4(uint32_t& r0, uint32_t& r1, uint32_t& r2, uint32_t& r3,
                                        uint32_t addr) {
    asm volatile("ldmatrix.sync.aligned.m8n8.x4.shared.b16 {%0,%1,%2,%3}, [%4];"
                 : "=r"(r0), "=r"(r1), "=r"(r2), "=r"(r3) : "r"(addr));
}
__device__ __forceinline__ void mma_fp16(float* c, uint32_t a0, uint32_t a1, uint32_t a2,
                                         uint32_t a3, uint32_t b0, uint32_t b1) {
    asm volatile("mma.sync.aligned.m16n8k16.row.col.f32.f16.f16.f32 "
                 "{%0,%1,%2,%3}, {%4,%5,%6,%7}, {%8,%9}, {%0,%1,%2,%3};"
                 : "+f"(c[0]), "+f"(c[1]), "+f"(c[2]), "+f"(c[3])
                 : "r"(a0), "r"(a1), "r"(a2), "r"(a3), "r"(b0), "r"(b1));
}

// ==================== weight transpose (once per launch) ====================
__global__ void wsplit_kernel(const float* __restrict__ W, __half* __restrict__ T,
                              int K, int N) {
    int i = blockIdx.x * blockDim.x + threadIdx.x;
    if (i >= K * N) return;
    int k = i / N, n = i % N;
    T[(size_t)n * K + k] = __float2half(W[i]);
}

// ==================== fp16 GEMM (layers 1 & 2, tanh epilogue) ====================
// C = tanh(A @ W^T + bias); A: fp16 [M,K] K-major; W: fp16 [N,K].
// K-chunks of 128 elements (256 B rows + 16 B pad), double-buffered cp.async.
#define ROWB 272

template<int BM, int BN>
__global__ __launch_bounds__(256)
void gemm_mma(const __half* __restrict__ A,
              const __half* __restrict__ B,
              const float* __restrict__ bias,
              __half* __restrict__ C, int N, int K)
{
    constexpr int WR = BM / 32;
    constexpr int WC = 8 / WR;
    constexpr int WN = BN / WC;
    constexpr int NT = WN / 8;
    constexpr int BUF = (BM + BN) * ROWB;
    static_assert(WR * WC == 8, "warp layout");

    extern __shared__ char smem[];
    const uint32_t sbase = smem_u32(smem);

    const int tid = threadIdx.x, wid = tid >> 5, lane = tid & 31;
    const int wm = wid % WR, wn = wid / WR;
    const int rowBase = blockIdx.y * BM;
    const int colBase = blockIdx.x * BN;

    const uint32_t offA = 0;
    const uint32_t offB = (uint32_t)BM * ROWB;

    const int nchunks = K >> 7;       // 128 elements per chunk

    auto load_chunk = [&](int c) {
        const uint32_t stage = sbase + (uint32_t)(c & 1) * BUF;
        const int kbase = c << 7;
        #pragma unroll
        for (int u = 0; u < BM * 16 / 256; u++) {
            int idx = tid + u * 256;
            int r = idx >> 4, q = idx & 15;
            size_t g = (size_t)(rowBase + r) * K + kbase + q * 8;
            cp_async16(stage + offA + (uint32_t)(r * ROWB + q * 16), A + g);
        }
        #pragma unroll
        for (int u = 0; u < BN * 16 / 256; u++) {
            int idx = tid + u * 256;
            int r = idx >> 4, q = idx & 15;
            size_t g = (size_t)(colBase + r) * K + kbase + q * 8;
            cp_async16(stage + offB + (uint32_t)(r * ROWB + q * 16), B + g);
        }
        cp_commit();
    };

    float acc[2][NT][4];
    #pragma unroll
    for (int mt = 0; mt < 2; mt++)
        #pragma unroll
        for (int nt = 0; nt < NT; nt++)
            #pragma unroll
            for (int j = 0; j < 4; j++)
                acc[mt][nt][j] = 0.0f;

    const int aRow = wm * 32 + (lane & 15);
    const int aByte = (lane & 16);
    const int bRow = wn * WN + ((lane & 16) >> 1) + (lane & 7);
    const int bByte = ((lane & 8) << 1);

    load_chunk(0);

    for (int c = 0; c < nchunks; c++) {
        if (c + 1 < nchunks) {
            load_chunk(c + 1);
            cp_wait<1>();
        } else {
            cp_wait<0>();
        }
        __syncthreads();

        const uint32_t stage = sbase + (uint32_t)(c & 1) * BUF;
        #pragma unroll
        for (int ks = 0; ks < 8; ks++) {
            uint32_t a[2][4];
            #pragma unroll
            for (int mt = 0; mt < 2; mt++) {
                uint32_t ad = stage + (uint32_t)((aRow + mt * 16) * ROWB + ks * 32 + aByte);
                ldsm_x4(a[mt][0], a[mt][1], a[mt][2], a[mt][3], ad + offA);
            }
            uint32_t bb[NT][2];
            #pragma unroll
            for (int nt2 = 0; nt2 < NT / 2; nt2++) {
                uint32_t bd = stage + (uint32_t)((bRow + nt2 * 16) * ROWB + ks * 32 + bByte);
                ldsm_x4(bb[nt2 * 2][0], bb[nt2 * 2][1], bb[nt2 * 2 + 1][0], bb[nt2 * 2 + 1][1],
                        bd + offB);
            }
            #pragma unroll
            for (int mt = 0; mt < 2; mt++)
                #pragma unroll
                for (int nt = 0; nt < NT; nt++)
                    mma_fp16(acc[mt][nt], a[mt][0], a[mt][1], a[mt][2], a[mt][3],
                             bb[nt][0], bb[nt][1]);
        }
        __syncthreads();
    }

    const int q = lane >> 2;
    const int p = lane & 3;
    #pragma unroll
    for (int mt = 0; mt < 2; mt++) {
        #pragma unroll
        for (int half = 0; half < 2; half++) {
            const int row = rowBase + wm * 32 + mt * 16 + q + half * 8;
            #pragma unroll
            for (int nt = 0; nt < NT; nt++) {
                const int col = colBase + wn * WN + nt * 8 + p * 2;
                float v0 = tanh_fast(acc[mt][nt][half * 2 + 0] + bias[col + 0]);
                float v1 = tanh_fast(acc[mt][nt][half * 2 + 1] + bias[col + 1]);
                *(__half2*)(C + (size_t)row * N + col) = __floats2half2_rn(v0, v1);
            }
        }
    }
}

// ==================== layer-3 GEMM with fused RK4 epilogue ====================
// EPI=1: k = acc+b3 -> kout (fp32); ytmp = y + coef*dt*k -> fp16 out.
// EPI=2: k4 = acc+b3; y_next = y + dt/6*(k1+2k2+2k3+k4) -> y, fp16 out, pred_y slice.
template<int EPI>
__global__ __launch_bounds__(256)
void gemm3_fused(const __half* __restrict__ A,
                 const __half* __restrict__ B,
                 const float* __restrict__ bias,
                 float* __restrict__ y,
                 float* __restrict__ kout,
                 const float* __restrict__ k1, const float* __restrict__ k2,
                 const float* __restrict__ k3,
                 __half* __restrict__ outq,
                 float* __restrict__ pred,
                 const float* __restrict__ t, int step, float coef,
                 int N, int K)
{
    constexpr int BM = 64, BN = 64;
    constexpr int WR = 2, WC = 4, WN = 16, NT = 2;
    constexpr int BUF = (BM + BN) * ROWB;

    extern __shared__ char smem[];
    const uint32_t sbase = smem_u32(smem);

    const int tid = threadIdx.x, wid = tid >> 5, lane = tid & 31;
    const int wm = wid % WR, wn = wid / WR;
    const int rowBase = blockIdx.y * BM;
    const int colBase = blockIdx.x * BN;

    const uint32_t offA = 0;
    const uint32_t offB = (uint32_t)BM * ROWB;

    const int nchunks = K >> 7;

    auto load_chunk = [&](int c) {
        const uint32_t stage = sbase + (uint32_t)(c & 1) * BUF;
        const int kbase = c << 7;
        #pragma unroll
        for (int u = 0; u < BM * 16 / 256; u++) {
            int idx = tid + u * 256;
            int r = idx >> 4, qq = idx & 15;
            size_t g = (size_t)(rowBase + r) * K + kbase + qq * 8;
            cp_async16(stage + offA + (uint32_t)(r * ROWB + qq * 16), A + g);
        }
        #pragma unroll
        for (int u = 0; u < BN * 16 / 256; u++) {
            int idx = tid + u * 256;
            int r = idx >> 4, qq = idx & 15;
            size_t g = (size_t)(colBase + r) * K + kbase + qq * 8;
            cp_async16(stage + offB + (uint32_t)(r * ROWB + qq * 16), B + g);
        }
        cp_commit();
    };

    float acc[2][NT][4];
    #pragma unroll
    for (int mt = 0; mt < 2; mt++)
        #pragma unroll
        for (int nt = 0; nt < NT; nt++)
            #pragma unroll
            for (int j = 0; j < 4; j++)
                acc[mt][nt][j] = 0.0f;

    const int aRow = wm * 32 + (lane & 15);
    const int aByte = (lane & 16);
    const int bRow = wn * WN + ((lane & 16) >> 1) + (lane & 7);
    const int bByte = ((lane & 8) << 1);

    load_chunk(0);

    for (int c = 0; c < nchunks; c++) {
        if (c + 1 < nchunks) {
            load_chunk(c + 1);
            cp_wait<1>();
        } else {
            cp_wait<0>();
        }
        __syncthreads();

        const uint32_t stage = sbase + (uint32_t)(c & 1) * BUF;
        #pragma unroll
        for (int ks = 0; ks < 8; ks++) {
            uint32_t a[2][4];
            #pragma unroll
            for (int mt = 0; mt < 2; mt++) {
                uint32_t ad = stage + (uint32_t)((aRow + mt * 16) * ROWB + ks * 32 + aByte);
                ldsm_x4(a[mt][0], a[mt][1], a[mt][2], a[mt][3], ad + offA);
            }
            uint32_t bb[NT][2];
            {
                uint32_t bd = stage + (uint32_t)(bRow * ROWB + ks * 32 + bByte);
                ldsm_x4(bb[0][0], bb[0][1], bb[1][0], bb[1][1], bd + offB);
            }
            #pragma unroll
            for (int mt = 0; mt < 2; mt++)
                #pragma unroll
                for (int nt = 0; nt < NT; nt++)
                    mma_fp16(acc[mt][nt], a[mt][0], a[mt][1], a[mt][2], a[mt][3],
                             bb[nt][0], bb[nt][1]);
        }
        __syncthreads();
    }

    const float dtv = t[step + 1] - t[step];
    const float cax = coef * dtv;
    const float s6 = dtv * (1.0f / 6.0f);
    const int q = lane >> 2;
    const int p = lane & 3;
    #pragma unroll
    for (int mt = 0; mt < 2; mt++) {
        #pragma unroll
        for (int half = 0; half < 2; half++) {
            const int row = rowBase + wm * 32 + mt * 16 + q + half * 8;
            #pragma unroll
            for (int nt = 0; nt < NT; nt++) {
                const int col = colBase + wn * WN + nt * 8 + p * 2;
                const size_t gi = (size_t)row * N + col;
                float kv0 = acc[mt][nt][half * 2 + 0] + bias[col + 0];
                float kv1 = acc[mt][nt][half * 2 + 1] + bias[col + 1];
                if (EPI == 1) {
                    *(float2*)(kout + gi) = make_float2(kv0, kv1);
                    float2 yv = *(const float2*)(y + gi);
                    float o0 = fmaf(cax, kv0, yv.x);
                    float o1 = fmaf(cax, kv1, yv.y);
                    *(__half2*)(outq + gi) = __floats2half2_rn(o0, o1);
                } else {
                    float2 yv = *(const float2*)(y + gi);
                    float2 a1 = *(const float2*)(k1 + gi);
                    float2 a2 = *(const float2*)(k2 + gi);
                    float2 a3 = *(const float2*)(k3 + gi);
                    float o0 = yv.x + s6 * (a1.x + 2.0f * a2.x + 2.0f * a3.x + kv0);
                    float o1 = yv.y + s6 * (a1.y + 2.0f * a2.y + 2.0f * a3.y + kv1);
                    *(float2*)(y + gi) = make_float2(o0, o1);
                    *(__half2*)(outq + gi) = __floats2half2_rn(o0, o1);
                    *(float2*)(pred + ((size_t)row * TPTS + (step + 1)) * DDIM + col) =
                        make_float2(o0, o1);
                }
            }
        }
    }
}

// ==================== init ====================
__global__ void init_kernel(const float* __restrict__ fp, float* __restrict__ y,
                            __half* __restrict__ yq,
                            float* __restrict__ out, int out_size)
{
    const int i = blockIdx.x * blockDim.x + threadIdx.x;
    float4 v = reinterpret_cast<const float4*>(fp)[i];
    reinterpret_cast<float4*>(y)[i] = v;
    const int e = i * 4;
    *(__half2*)(yq + e + 0) = __floats2half2_rn(v.x, v.y);
    *(__half2*)(yq + e + 2) = __floats2half2_rn(v.z, v.w);
    const int row = e / DDIM;
    const int col = e % DDIM;
    *reinterpret_cast<float4*>(&out[(size_t)row * TPTS * DDIM + col]) = v;
    if (i == 0) {
        const int base = MROWS * TPTS * DDIM;
        for (int z = base; z < out_size; z++) out[z] = 0.0f;
    }
}

// ==================== launch ====================
#define SMEM_12 (2 * (128 + 128) * ROWB)    // 139264
#define SMEM_3  (2 * (64 + 64) * ROWB)      // 69632

extern "C" void kernel_launch(void* const* d_in, const int* in_sizes, int n_in,
                              void* d_out, int out_size)
{
    const float* fp = (const float*)d_in[0];
    const float* t  = (const float*)d_in[1];
    const float* W1 = (const float*)d_in[2];
    const float* b1 = (const float*)d_in[3];
    const float* W2 = (const float*)d_in[4];
    const float* b2 = (const float*)d_in[5];
    const float* W3 = (const float*)d_in[6];
    const float* b3 = (const float*)d_in[7];
    float* out = (float*)d_out;

    float *y, *k1, *k2, *k3;
    __half *yq, *ytq, *h1q, *h2q, *w1, *w2, *w3;
    cudaGetSymbolAddress((void**)&y,   g_y);
    cudaGetSymbolAddress((void**)&k1,  g_k1);
    cudaGetSymbolAddress((void**)&k2,  g_k2);
    cudaGetSymbolAddress((void**)&k3,  g_k3);
    cudaGetSymbolAddress((void**)&yq,  g_yq);
    cudaGetSymbolAddress((void**)&ytq, g_ytq);
    cudaGetSymbolAddress((void**)&h1q, g_h1q);
    cudaGetSymbolAddress((void**)&h2q, g_h2q);
    cudaGetSymbolAddress((void**)&w1,  g_w1);
    cudaGetSymbolAddress((void**)&w2,  g_w2);
    cudaGetSymbolAddress((void**)&w3,  g_w3);

    cudaFuncSetAttribute((const void*)gemm_mma<128, 128>,
                         cudaFuncAttributeMaxDynamicSharedMemorySize, SMEM_12);
    cudaFuncSetAttribute((const void*)gemm3_fused<1>,
                         cudaFuncAttributeMaxDynamicSharedMemorySize, SMEM_3);
    cudaFuncSetAttribute((const void*)gemm3_fused<2>,
                         cudaFuncAttributeMaxDynamicSharedMemorySize, SMEM_3);

    wsplit_kernel<<<(DDIM * HDIM + 255) / 256, 256>>>(W1, w1, DDIM, HDIM);
    wsplit_kernel<<<(HDIM * HDIM + 255) / 256, 256>>>(W2, w2, HDIM, HDIM);
    wsplit_kernel<<<(HDIM * DDIM + 255) / 256, 256>>>(W3, w3, HDIM, DDIM);

    const int NV4 = (MROWS * DDIM) / 4;
    const dim3 ew_grid(NV4 / 256);
    init_kernel<<<ew_grid, 256>>>(fp, y, yq, out, out_size);

    const dim3 g12(HDIM / 128, MROWS / 128);    // 8 x 16 = 128 CTAs
    const dim3 g3(DDIM / 64, MROWS / 64);       // 4 x 32 = 128 CTAs

    auto mlp12 = [&](const __half* x) {
        gemm_mma<128, 128><<<g12, 256, SMEM_12>>>(x, w1, b1, h1q, HDIM, DDIM);
        gemm_mma<128, 128><<<g12, 256, SMEM_12>>>(h1q, w2, b2, h2q, HDIM, HDIM);
    };

    for (int s = 0; s < NSTEPS; s++) {
        mlp12(yq);
        gemm3_fused<1><<<g3, 256, SMEM_3>>>(h2q, w3, b3, y, k1,
                                            nullptr, nullptr, nullptr,
                                            ytq, nullptr, t, s, 0.5f, DDIM, HDIM);
        mlp12(ytq);
        gemm3_fused<1><<<g3, 256, SMEM_3>>>(h2q, w3, b3, y, k2,
                                            nullptr, nullptr, nullptr,
                                            ytq, nullptr, t, s, 0.5f, DDIM, HDIM);
        mlp12(ytq);
        gemm3_fused<1><<<g3, 256, SMEM_3>>>(h2q, w3, b3, y, k3,
                                            nullptr, nullptr, nullptr,
                                            ytq, nullptr, t, s, 1.0f, DDIM, HDIM);
        mlp12(ytq);
        gemm3_fused<2><<<g3, 256, SMEM_3>>>(h2q, w3, b3, y, nullptr,
                                            k1, k2, k3,
                                            yq, out, t, s, 0.0f, DDIM, HDIM);
    }
}

// round 14
// speedup vs baseline: 1.1333x; 1.0182x over previous
#include <cuda_runtime.h>
#include <cuda_fp16.h>
#include <cstdint>

// Problem dims: S=4, B=512 -> M=2048; D=256; H=1024; T=50 -> 49 RK4 steps
#define MROWS 2048
#define DDIM  256
#define HDIM  1024
#define TPTS  50
#define NSTEPS (TPTS - 1)

// ==================== device scratch ====================
__device__ float g_y [MROWS * DDIM];
__device__ float g_k1[MROWS * DDIM];
__device__ float g_k2[MROWS * DDIM];
__device__ float g_k3[MROWS * DDIM];
__device__ __half g_yq [MROWS * DDIM];
__device__ __half g_ytq[MROWS * DDIM];
__device__ __half g_h1q[MROWS * HDIM];
__device__ __half g_h2q[MROWS * HDIM];
__device__ __half g_w1[HDIM * DDIM];
__device__ __half g_w2[HDIM * HDIM];
__device__ __half g_w3[DDIM * HDIM];

// fast tanh: 1 - 2/(e^{2x}+1)
__device__ __forceinline__ float tanh_fast(float x) {
    float e;
    asm("ex2.approx.f32 %0, %1;" : "=f"(e) : "f"(x * 2.8853900817779268f));
    float r;
    asm("rcp.approx.f32 %0, %1;" : "=f"(r) : "f"(e + 1.0f));
    return fmaf(-2.0f, r, 1.0f);
}

__device__ __forceinline__ uint32_t smem_u32(const void* p) {
    uint32_t a;
    asm("{ .reg .u64 t; cvta.to.shared.u64 t, %1; cvt.u32.u64 %0, t; }" : "=r"(a) : "l"(p));
    return a;
}
__device__ __forceinline__ void cp_async16(uint32_t dst, const void* src) {
    asm volatile("cp.async.cg.shared.global [%0], [%1], 16;" :: "r"(dst), "l"(src) : "memory");
}
__device__ __forceinline__ void cp_commit() {
    asm volatile("cp.async.commit_group;" ::: "memory");
}
template<int N>
__device__ __forceinline__ void cp_wait() {
    asm volatile("cp.async.wait_group %0;" :: "n"(N) : "memory");
}
__device__ __forceinline__ void ldsm_x4(uint32_t& r0, uint32_t& r1, uint32_t& r2, uint32_t& r3,
                                        uint32_t addr) {
    asm volatile("ldmatrix.sync.aligned.m8n8.x4.shared.b16 {%0,%1,%2,%3}, [%4];"
                 : "=r"(r0), "=r"(r1), "=r"(r2), "=r"(r3) : "r"(addr));
}
__device__ __forceinline__ void mma_fp16(float* c, uint32_t a0, uint32_t a1, uint32_t a2,
                                         uint32_t a3, uint32_t b0, uint32_t b1) {
    asm volatile("mma.sync.aligned.m16n8k16.row.col.f32.f16.f16.f32 "
                 "{%0,%1,%2,%3}, {%4,%5,%6,%7}, {%8,%9}, {%0,%1,%2,%3};"
                 : "+f"(c[0]), "+f"(c[1]), "+f"(c[2]), "+f"(c[3])
                 : "r"(a0), "r"(a1), "r"(a2), "r"(a3), "r"(b0), "r"(b1));
}

// ==================== weight transpose (once per launch) ====================
__global__ void wsplit_kernel(const float* __restrict__ W, __half* __restrict__ T,
                              int K, int N) {
    int i = blockIdx.x * blockDim.x + threadIdx.x;
    if (i >= K * N) return;
    int k = i / N, n = i % N;
    T[(size_t)n * K + k] = __float2half(W[i]);
}

// ==================== fp16 GEMM (layers 1 & 2, tanh epilogue) ====================
// C = tanh(A @ W^T + bias); A: fp16 [M,K] K-major; W: fp16 [N,K].
// K-chunks of 128 elements (256 B rows + 16 B pad), double-buffered cp.async.
#define ROWB 272

template<int BM, int BN>
__global__ __launch_bounds__(256)
void gemm_mma(const __half* __restrict__ A,
              const __half* __restrict__ B,
              const float* __restrict__ bias,
              __half* __restrict__ C, int N, int K)
{
    constexpr int WR = BM / 32;
    constexpr int WC = 8 / WR;
    constexpr int WN = BN / WC;
    constexpr int NT = WN / 8;
    constexpr int BUF = (BM + BN) * ROWB;
    static_assert(WR * WC == 8, "warp layout");

    extern __shared__ char smem[];
    const uint32_t sbase = smem_u32(smem);

    const int tid = threadIdx.x, wid = tid >> 5, lane = tid & 31;
    const int wm = wid % WR, wn = wid / WR;
    const int rowBase = blockIdx.y * BM;
    const int colBase = blockIdx.x * BN;

    const uint32_t offA = 0;
    const uint32_t offB = (uint32_t)BM * ROWB;

    const int nchunks = K >> 7;       // 128 elements per chunk

    auto load_chunk = [&](int c) {
        const uint32_t stage = sbase + (uint32_t)(c & 1) * BUF;
        const int kbase = c << 7;
        #pragma unroll
        for (int u = 0; u < BM * 16 / 256; u++) {
            int idx = tid + u * 256;
            int r = idx >> 4, q = idx & 15;
            size_t g = (size_t)(rowBase + r) * K + kbase + q * 8;
            cp_async16(stage + offA + (uint32_t)(r * ROWB + q * 16), A + g);
        }
        #pragma unroll
        for (int u = 0; u < BN * 16 / 256; u++) {
            int idx = tid + u * 256;
            int r = idx >> 4, q = idx & 15;
            size_t g = (size_t)(colBase + r) * K + kbase + q * 8;
            cp_async16(stage + offB + (uint32_t)(r * ROWB + q * 16), B + g);
        }
        cp_commit();
    };

    float acc[2][NT][4];
    #pragma unroll
    for (int mt = 0; mt < 2; mt++)
        #pragma unroll
        for (int nt = 0; nt < NT; nt++)
            #pragma unroll
            for (int j = 0; j < 4; j++)
                acc[mt][nt][j] = 0.0f;

    const int aRow = wm * 32 + (lane & 15);
    const int aByte = (lane & 16);
    const int bRow = wn * WN + ((lane & 16) >> 1) + (lane & 7);
    const int bByte = ((lane & 8) << 1);

    load_chunk(0);

    for (int c = 0; c < nchunks; c++) {
        if (c + 1 < nchunks) {
            load_chunk(c + 1);
            cp_wait<1>();
        } else {
            cp_wait<0>();
        }
        __syncthreads();

        const uint32_t stage = sbase + (uint32_t)(c & 1) * BUF;
        #pragma unroll
        for (int ks = 0; ks < 8; ks++) {
            uint32_t a[2][4];
            #pragma unroll
            for (int mt = 0; mt < 2; mt++) {
                uint32_t ad = stage + (uint32_t)((aRow + mt * 16) * ROWB + ks * 32 + aByte);
                ldsm_x4(a[mt][0], a[mt][1], a[mt][2], a[mt][3], ad + offA);
            }
            uint32_t bb[NT][2];
            #pragma unroll
            for (int nt2 = 0; nt2 < NT / 2; nt2++) {
                uint32_t bd = stage + (uint32_t)((bRow + nt2 * 16) * ROWB + ks * 32 + bByte);
                ldsm_x4(bb[nt2 * 2][0], bb[nt2 * 2][1], bb[nt2 * 2 + 1][0], bb[nt2 * 2 + 1][1],
                        bd + offB);
            }
            #pragma unroll
            for (int mt = 0; mt < 2; mt++)
                #pragma unroll
                for (int nt = 0; nt < NT; nt++)
                    mma_fp16(acc[mt][nt], a[mt][0], a[mt][1], a[mt][2], a[mt][3],
                             bb[nt][0], bb[nt][1]);
        }
        if (c + 1 < nchunks) __syncthreads();   // protects buffer reuse at distance 2
    }

    const int q = lane >> 2;
    const int p = lane & 3;
    #pragma unroll
    for (int mt = 0; mt < 2; mt++) {
        #pragma unroll
        for (int half = 0; half < 2; half++) {
            const int row = rowBase + wm * 32 + mt * 16 + q + half * 8;
            #pragma unroll
            for (int nt = 0; nt < NT; nt++) {
                const int col = colBase + wn * WN + nt * 8 + p * 2;
                float v0 = tanh_fast(acc[mt][nt][half * 2 + 0] + bias[col + 0]);
                float v1 = tanh_fast(acc[mt][nt][half * 2 + 1] + bias[col + 1]);
                *(__half2*)(C + (size_t)row * N + col) = __floats2half2_rn(v0, v1);
            }
        }
    }
}

// ==================== layer-3 GEMM with fused RK4 epilogue ====================
// K-chunks of 256 elements (512 B rows + 16 B pad) -> 4 chunks for K=1024.
// EPI=1: k = acc+b3 -> kout (fp32); ytmp = y + coef*dt*k -> fp16 out.
// EPI=2: k4 = acc+b3; y_next = y + dt/6*(k1+2k2+2k3+k4) -> y, fp16 out, pred_y slice.
#define ROWB3 528

template<int EPI>
__global__ __launch_bounds__(256)
void gemm3_fused(const __half* __restrict__ A,
                 const __half* __restrict__ B,
                 const float* __restrict__ bias,
                 float* __restrict__ y,
                 float* __restrict__ kout,
                 const float* __restrict__ k1, const float* __restrict__ k2,
                 const float* __restrict__ k3,
                 __half* __restrict__ outq,
                 float* __restrict__ pred,
                 const float* __restrict__ t, int step, float coef,
                 int N, int K)
{
    constexpr int BM = 64, BN = 64;
    constexpr int WR = 2, WC = 4, WN = 16, NT = 2;
    constexpr int BUF = (BM + BN) * ROWB3;

    extern __shared__ char smem[];
    const uint32_t sbase = smem_u32(smem);

    const int tid = threadIdx.x, wid = tid >> 5, lane = tid & 31;
    const int wm = wid % WR, wn = wid / WR;
    const int rowBase = blockIdx.y * BM;
    const int colBase = blockIdx.x * BN;

    const uint32_t offA = 0;
    const uint32_t offB = (uint32_t)BM * ROWB3;

    const int nchunks = K >> 8;       // 256 elements per chunk

    auto load_chunk = [&](int c) {
        const uint32_t stage = sbase + (uint32_t)(c & 1) * BUF;
        const int kbase = c << 8;
        #pragma unroll
        for (int u = 0; u < BM * 32 / 256; u++) {
            int idx = tid + u * 256;
            int r = idx >> 5, qq = idx & 31;
            size_t g = (size_t)(rowBase + r) * K + kbase + qq * 8;
            cp_async16(stage + offA + (uint32_t)(r * ROWB3 + qq * 16), A + g);
        }
        #pragma unroll
        for (int u = 0; u < BN * 32 / 256; u++) {
            int idx = tid + u * 256;
            int r = idx >> 5, qq = idx & 31;
            size_t g = (size_t)(colBase + r) * K + kbase + qq * 8;
            cp_async16(stage + offB + (uint32_t)(r * ROWB3 + qq * 16), B + g);
        }
        cp_commit();
    };

    float acc[2][NT][4];
    #pragma unroll
    for (int mt = 0; mt < 2; mt++)
        #pragma unroll
        for (int nt = 0; nt < NT; nt++)
            #pragma unroll
            for (int j = 0; j < 4; j++)
                acc[mt][nt][j] = 0.0f;

    const int aRow = wm * 32 + (lane & 15);
    const int aByte = (lane & 16);
    const int bRow = wn * WN + ((lane & 16) >> 1) + (lane & 7);
    const int bByte = ((lane & 8) << 1);

    load_chunk(0);

    for (int c = 0; c < nchunks; c++) {
        if (c + 1 < nchunks) {
            load_chunk(c + 1);
            cp_wait<1>();
        } else {
            cp_wait<0>();
        }
        __syncthreads();

        const uint32_t stage = sbase + (uint32_t)(c & 1) * BUF;
        #pragma unroll
        for (int ks = 0; ks < 16; ks++) {
            uint32_t a[2][4];
            #pragma unroll
            for (int mt = 0; mt < 2; mt++) {
                uint32_t ad = stage + (uint32_t)((aRow + mt * 16) * ROWB3 + ks * 32 + aByte);
                ldsm_x4(a[mt][0], a[mt][1], a[mt][2], a[mt][3], ad + offA);
            }
            uint32_t bb[NT][2];
            {
                uint32_t bd = stage + (uint32_t)(bRow * ROWB3 + ks * 32 + bByte);
                ldsm_x4(bb[0][0], bb[0][1], bb[1][0], bb[1][1], bd + offB);
            }
            #pragma unroll
            for (int mt = 0; mt < 2; mt++)
                #pragma unroll
                for (int nt = 0; nt < NT; nt++)
                    mma_fp16(acc[mt][nt], a[mt][0], a[mt][1], a[mt][2], a[mt][3],
                             bb[nt][0], bb[nt][1]);
        }
        if (c + 1 < nchunks) __syncthreads();
    }

    const float dtv = t[step + 1] - t[step];
    const float cax = coef * dtv;
    const float s6 = dtv * (1.0f / 6.0f);
    const int q = lane >> 2;
    const int p = lane & 3;
    #pragma unroll
    for (int mt = 0; mt < 2; mt++) {
        #pragma unroll
        for (int half = 0; half < 2; half++) {
            const int row = rowBase + wm * 32 + mt * 16 + q + half * 8;
            #pragma unroll
            for (int nt = 0; nt < NT; nt++) {
                const int col = colBase + wn * WN + nt * 8 + p * 2;
                const size_t gi = (size_t)row * N + col;
                float kv0 = acc[mt][nt][half * 2 + 0] + bias[col + 0];
                float kv1 = acc[mt][nt][half * 2 + 1] + bias[col + 1];
                if (EPI == 1) {
                    *(float2*)(kout + gi) = make_float2(kv0, kv1);
                    float2 yv = *(const float2*)(y + gi);
                    float o0 = fmaf(cax, kv0, yv.x);
                    float o1 = fmaf(cax, kv1, yv.y);
                    *(__half2*)(outq + gi) = __floats2half2_rn(o0, o1);
                } else {
                    float2 yv = *(const float2*)(y + gi);
                    float2 a1 = *(const float2*)(k1 + gi);
                    float2 a2 = *(const float2*)(k2 + gi);
                    float2 a3 = *(const float2*)(k3 + gi);
                    float o0 = yv.x + s6 * (a1.x + 2.0f * a2.x + 2.0f * a3.x + kv0);
                    float o1 = yv.y + s6 * (a1.y + 2.0f * a2.y + 2.0f * a3.y + kv1);
                    *(float2*)(y + gi) = make_float2(o0, o1);
                    *(__half2*)(outq + gi) = __floats2half2_rn(o0, o1);
                    *(float2*)(pred + ((size_t)row * TPTS + (step + 1)) * DDIM + col) =
                        make_float2(o0, o1);
                }
            }
        }
    }
}

// ==================== init ====================
__global__ void init_kernel(const float* __restrict__ fp, float* __restrict__ y,
                            __half* __restrict__ yq,
                            float* __restrict__ out, int out_size)
{
    const int i = blockIdx.x * blockDim.x + threadIdx.x;
    float4 v = reinterpret_cast<const float4*>(fp)[i];
    reinterpret_cast<float4*>(y)[i] = v;
    const int e = i * 4;
    *(__half2*)(yq + e + 0) = __floats2half2_rn(v.x, v.y);
    *(__half2*)(yq + e + 2) = __floats2half2_rn(v.z, v.w);
    const int row = e / DDIM;
    const int col = e % DDIM;
    *reinterpret_cast<float4*>(&out[(size_t)row * TPTS * DDIM + col]) = v;
    if (i == 0) {
        const int base = MROWS * TPTS * DDIM;
        for (int z = base; z < out_size; z++) out[z] = 0.0f;
    }
}

// ==================== launch ====================
#define SMEM_12 (2 * (128 + 128) * ROWB)     // 139264
#define SMEM_3  (2 * (64 + 64) * ROWB3)      // 135168

extern "C" void kernel_launch(void* const* d_in, const int* in_sizes, int n_in,
                              void* d_out, int out_size)
{
    const float* fp = (const float*)d_in[0];
    const float* t  = (const float*)d_in[1];
    const float* W1 = (const float*)d_in[2];
    const float* b1 = (const float*)d_in[3];
    const float* W2 = (const float*)d_in[4];
    const float* b2 = (const float*)d_in[5];
    const float* W3 = (const float*)d_in[6];
    const float* b3 = (const float*)d_in[7];
    float* out = (float*)d_out;

    float *y, *k1, *k2, *k3;
    __half *yq, *ytq, *h1q, *h2q, *w1, *w2, *w3;
    cudaGetSymbolAddress((void**)&y,   g_y);
    cudaGetSymbolAddress((void**)&k1,  g_k1);
    cudaGetSymbolAddress((void**)&k2,  g_k2);
    cudaGetSymbolAddress((void**)&k3,  g_k3);
    cudaGetSymbolAddress((void**)&yq,  g_yq);
    cudaGetSymbolAddress((void**)&ytq, g_ytq);
    cudaGetSymbolAddress((void**)&h1q, g_h1q);
    cudaGetSymbolAddress((void**)&h2q, g_h2q);
    cudaGetSymbolAddress((void**)&w1,  g_w1);
    cudaGetSymbolAddress((void**)&w2,  g_w2);
    cudaGetSymbolAddress((void**)&w3,  g_w3);

    cudaFuncSetAttribute((const void*)gemm_mma<128, 128>,
                         cudaFuncAttributeMaxDynamicSharedMemorySize, SMEM_12);
    cudaFuncSetAttribute((const void*)gemm3_fused<1>,
                         cudaFuncAttributeMaxDynamicSharedMemorySize, SMEM_3);
    cudaFuncSetAttribute((const void*)gemm3_fused<2>,
                         cudaFuncAttributeMaxDynamicSharedMemorySize, SMEM_3);

    wsplit_kernel<<<(DDIM * HDIM + 255) / 256, 256>>>(W1, w1, DDIM, HDIM);
    wsplit_kernel<<<(HDIM * HDIM + 255) / 256, 256>>>(W2, w2, HDIM, HDIM);
    wsplit_kernel<<<(HDIM * DDIM + 255) / 256, 256>>>(W3, w3, HDIM, DDIM);

    const int NV4 = (MROWS * DDIM) / 4;
    const dim3 ew_grid(NV4 / 256);
    init_kernel<<<ew_grid, 256>>>(fp, y, yq, out, out_size);

    const dim3 g12(HDIM / 128, MROWS / 128);    // 8 x 16 = 128 CTAs
    const dim3 g3(DDIM / 64, MROWS / 64);       // 4 x 32 = 128 CTAs

    auto mlp12 = [&](const __half* x) {
        gemm_mma<128, 128><<<g12, 256, SMEM_12>>>(x, w1, b1, h1q, HDIM, DDIM);
        gemm_mma<128, 128><<<g12, 256, SMEM_12>>>(h1q, w2, b2, h2q, HDIM, HDIM);
    };

    for (int s = 0; s < NSTEPS; s++) {
        mlp12(yq);
        gemm3_fused<1><<<g3, 256, SMEM_3>>>(h2q, w3, b3, y, k1,
                                            nullptr, nullptr, nullptr,
                                            ytq, nullptr, t, s, 0.5f, DDIM, HDIM);
        mlp12(ytq);
        gemm3_fused<1><<<g3, 256, SMEM_3>>>(h2q, w3, b3, y, k2,
                                            nullptr, nullptr, nullptr,
                                            ytq, nullptr, t, s, 0.5f, DDIM, HDIM);
        mlp12(ytq);
        gemm3_fused<1><<<g3, 256, SMEM_3>>>(h2q, w3, b3, y, k3,
                                            nullptr, nullptr, nullptr,
                                            ytq, nullptr, t, s, 1.0f, DDIM, HDIM);
        mlp12(ytq);
        gemm3_fused<2><<<g3, 256, SMEM_3>>>(h2q, w3, b3, y, nullptr,
                                            k1, k2, k3,
                                            yq, out, t, s, 0.0f, DDIM, HDIM);
    }
}